// round 10
// baseline (speedup 1.0000x reference)
#include <cuda_runtime.h>
#include <math.h>

#define BB 1323u            // batch == NPTS
#define DM 1024             // DMODEL
#define NTOT (BB * BB)      // 1,750,329 points
#define NCHUNK ((NTOT + 3) / 4)   // 437,583 4-point chunks
#define NBLK 1184u
#define TPB 256u
#define TTOT (NBLK * TPB)         // 303,104 threads
#define LOG_2PI 1.8378770664093453f
#define LOG2E   1.4426950408889634f
#define NEG_HALF_LOG2E (-0.7213475204444817f)

__device__ __align__(16) float g_params[BB * 16];

__device__ __forceinline__ float softplus_f(float x) {
    return fmaxf(x, 0.0f) + log1pf(__expf(-fabsf(x)));
}

// exp2 without MUFU: magic-add rounding + degree-5 poly + exponent splice.
// input y = log2 of result; valid for y in [-126, 127]; clamped below.
__device__ __forceinline__ float exp2_fma(float y) {
    y = fmaxf(y, -126.0f);                       // underflow -> ~2^-126 (~1e-38)
    float z = y + 12582912.0f;                   // 1.5*2^23: round-to-nearest int
    int   n = __float_as_int(z) - 0x4B400000;    // low bits hold the integer
    float f = y - (z - 12582912.0f);             // f in [-0.5, 0.5]
    // 2^f = e^(f ln2), degree-5 Taylor, rel err ~2e-6 on [-0.5,0.5]
    float p = 1.3333558146e-3f;
    p = fmaf(p, f, 9.6181291076e-3f);
    p = fmaf(p, f, 5.5504108664e-2f);
    p = fmaf(p, f, 2.4022650696e-1f);
    p = fmaf(p, f, 6.9314718056e-1f);
    p = fmaf(p, f, 1.0f);
    return __int_as_float(__float_as_int(p) + (n << 23));
}

// ---------------- kernel 1: params. 148 blocks x 9 warps (one block/SM) ----------------
__global__ __launch_bounds__(288)
void mvn3d_params_kernel(const float* __restrict__ rep,
                         const float* __restrict__ Wm,
                         const float* __restrict__ bm,
                         const float* __restrict__ Ws,
                         const float* __restrict__ bs,
                         float* __restrict__ out)
{
#if __CUDA_ARCH__ >= 900
    cudaTriggerProgrammaticLaunchCompletion();
#endif

    __shared__ __align__(16) float sW[9 * DM];       // 36 KB
    float4* sW4 = (float4*)sW;

    const int tid  = threadIdx.x;
    const int warp = tid >> 5;
    const int lane = tid & 31;

    {
        const float4* Wm4 = (const float4*)Wm;   // 768 float4
        const float4* Ws4 = (const float4*)Ws;   // 1536 float4
        #pragma unroll
        for (int c = 0; c < 8; c++) {
            int t2 = c * 288 + tid;
            sW4[t2] = (t2 < 768) ? Wm4[t2] : Ws4[t2 - 768];
        }
    }
    __syncthreads();

    unsigned row = (unsigned)warp * 148u + blockIdx.x;
    if (warp == 8) row = 1184u + blockIdx.x;
    if (row >= BB) return;

    float acc[9];
    #pragma unroll
    for (int a = 0; a < 9; a++) acc[a] = 0.0f;

    const float4* r4 = (const float4*)(rep + (size_t)row * DM);
    #pragma unroll 2
    for (int c = 0; c < 8; c++) {
        int idx = c * 32 + lane;
        float4 rv = r4[idx];
        #pragma unroll
        for (int a = 0; a < 9; a++) {
            float4 w = sW4[a * 256 + idx];
            acc[a] = fmaf(rv.x, w.x, fmaf(rv.y, w.y, fmaf(rv.z, w.z, fmaf(rv.w, w.w, acc[a]))));
        }
    }

    #pragma unroll
    for (int a = 0; a < 9; a++) {
        #pragma unroll
        for (int off = 16; off > 0; off >>= 1)
            acc[a] += __shfl_down_sync(0xffffffffu, acc[a], off);
    }

    if (lane == 0) {
        float mx  = acc[0] + bm[0];
        float my  = acc[1] + bm[1];
        float mz  = acc[2] + bm[2];
        float L00 = softplus_f(acc[3] + bs[0]);
        float L10 = acc[4] + bs[1];
        float L11 = softplus_f(acc[5] + bs[2]);
        float L20 = acc[6] + bs[3];
        float L21 = acc[7] + bs[4];
        float L22 = softplus_f(acc[8] + bs[5]);

        // store c pre-scaled to base-2: log_prob*log2e = -0.5*log2e*M + c2
        float c  = -(logf(L00) + logf(L11) + logf(L22)) - 1.5f * LOG_2PI;
        float c2 = c * LOG2E;

        float4* P = (float4*)(g_params + (size_t)row * 16);
        P[0] = make_float4(mx, my, mz, 1.0f / L00);
        P[1] = make_float4(L10, 1.0f / L11, L20, L21);
        P[2] = make_float4(1.0f / L22, c2, 0.0f, 0.0f);

        float* Lout = out + (size_t)NTOT + (size_t)row * 9;
        Lout[0] = L00; Lout[1] = 0.0f; Lout[2] = 0.0f;
        Lout[3] = L10; Lout[4] = L11; Lout[5] = 0.0f;
        Lout[6] = L20; Lout[7] = L21; Lout[8] = L22;
    }
}

// ---------------- kernel 2: profile (PDL secondary) ----------------
__device__ __forceinline__ float mvn_eval(float d0, float d1, float d2,
                                          const float4& P0, const float4& P1,
                                          const float4& P2)
{
    float y0 = (d0 - P0.x) * P0.w;
    float y1 = (d1 - P0.y - P1.x * y0) * P1.y;
    float y2 = (d2 - P0.z - P1.z * y0 - P1.w * y1) * P2.x;
    float M  = fmaf(y0, y0, fmaf(y1, y1, y2 * y2));
    // P2.y = c*log2e ; exp(log_prob) = 2^( -0.5*log2e*M + c2 )
    return exp2_fma(fmaf(M, NEG_HALF_LOG2E, P2.y));
}

__device__ __forceinline__ void chunk_eval(unsigned p0, const float* d,
                                           float* __restrict__ out)
{
    unsigned i = p0 / BB;
    unsigned j = p0 - i * BB;
    const float4* P = (const float4*)(g_params + (size_t)i * 16);
    float4 P0 = P[0], P1 = P[1], P2 = P[2];

    float4 res;
    float* rp = &res.x;
    #pragma unroll
    for (int k = 0; k < 4; k++) {
        if (j >= BB) {
            j -= BB;
            P = (const float4*)(g_params + (size_t)(++i) * 16);
            P0 = P[0]; P1 = P[1]; P2 = P[2];
        }
        rp[k] = mvn_eval(d[3*k], d[3*k+1], d[3*k+2], P0, P1, P2);
        j++;
    }
    *(float4*)(out + p0) = res;
}

__device__ __forceinline__ void tail_eval(unsigned pStart,
                                          const float* __restrict__ dxyz,
                                          float* __restrict__ out)
{
    for (unsigned p = pStart; p < NTOT; p++) {
        unsigned i = p / BB;
        const float4* P = (const float4*)(g_params + (size_t)i * 16);
        out[p] = mvn_eval(dxyz[3*p], dxyz[3*p+1], dxyz[3*p+2], P[0], P[1], P[2]);
    }
}

__global__ __launch_bounds__(TPB)
void mvn3d_profile_kernel(const float* __restrict__ dxyz,
                          float* __restrict__ out)
{
    const unsigned t = blockIdx.x * TPB + threadIdx.x;

    const unsigned pA = t * 4;
    const unsigned pB = (t + TTOT) * 4;

    const bool hasB  = (t + TTOT < NCHUNK);
    const bool fullA = (pA + 3 < NTOT);
    const bool fullB = hasB && (pB + 3 < NTOT);

    // front-batch dxyz loads — overlaps with the still-running params kernel
    float4 vA[3], vB[3];
    if (fullA) {
        const float4* dv = (const float4*)(dxyz + (size_t)pA * 3);
        vA[0] = dv[0]; vA[1] = dv[1]; vA[2] = dv[2];
    }
    if (fullB) {
        const float4* dv = (const float4*)(dxyz + (size_t)pB * 3);
        vB[0] = dv[0]; vB[1] = dv[1]; vB[2] = dv[2];
    }

#if __CUDA_ARCH__ >= 900
    cudaGridDependencySynchronize();
#endif

    if (fullA)           chunk_eval(pA, (const float*)vA, out);
    else if (pA < NTOT)  tail_eval(pA, dxyz, out);

    if (fullB)                   chunk_eval(pB, (const float*)vB, out);
    else if (hasB && pB < NTOT)  tail_eval(pB, dxyz, out);
}

extern "C" void kernel_launch(void* const* d_in, const int* in_sizes, int n_in,
                              void* d_out, int out_size) {
    const float* rep  = (const float*)d_in[0];
    const float* dxyz = (const float*)d_in[1];
    const float* Wm   = (const float*)d_in[2];
    const float* bm   = (const float*)d_in[3];
    const float* Ws   = (const float*)d_in[4];
    const float* bs   = (const float*)d_in[5];
    float* out = (float*)d_out;

    mvn3d_params_kernel<<<148, 288>>>(rep, Wm, bm, Ws, bs, out);

    cudaLaunchConfig_t cfg = {};
    cfg.gridDim  = dim3(NBLK);
    cfg.blockDim = dim3(TPB);
    cudaLaunchAttribute attr[1];
    attr[0].id = cudaLaunchAttributeProgrammaticStreamSerialization;
    attr[0].val.programmaticStreamSerializationAllowed = 1;
    cfg.attrs = attr;
    cfg.numAttrs = 1;
    cudaLaunchKernelEx(&cfg, mvn3d_profile_kernel, dxyz, out);
}

// round 13
// speedup vs baseline: 1.0619x; 1.0619x over previous
#include <cuda_runtime.h>
#include <math.h>

#define BB 1323u            // batch == NPTS
#define DM 1024             // DMODEL
#define NTOT (BB * BB)      // 1,750,329 points
#define NCHUNK ((NTOT + 3) / 4)   // 437,583 4-point chunks
#define NBLK 1184u
#define TPB 256u
#define TTOT (NBLK * TPB)         // 303,104 threads
#define LOG_2PI 1.8378770664093453f

__device__ __align__(16) float g_params[BB * 16];

__device__ __forceinline__ float softplus_f(float x) {
    return fmaxf(x, 0.0f) + log1pf(__expf(-fabsf(x)));
}

// ---------------- kernel 1: params. 148 blocks x 9 warps (one block/SM) ----------------
__global__ __launch_bounds__(288)
void mvn3d_params_kernel(const float* __restrict__ rep,
                         const float* __restrict__ Wm,
                         const float* __restrict__ bm,
                         const float* __restrict__ Ws,
                         const float* __restrict__ bs,
                         float* __restrict__ out)
{
#if __CUDA_ARCH__ >= 900
    cudaTriggerProgrammaticLaunchCompletion();
#endif

    __shared__ __align__(16) float sW[9 * DM];       // 36 KB
    float4* sW4 = (float4*)sW;

    const int tid  = threadIdx.x;
    const int warp = tid >> 5;
    const int lane = tid & 31;

    unsigned row = (unsigned)warp * 148u + blockIdx.x;
    if (warp == 8) row = 1184u + blockIdx.x;
    const bool live = (row < BB);

    // FRONT-BATCH the full rep row: 8 outstanding LDG.128 per warp.
    // This is the MLP fix: rep (5.4 MB) now streams at the LTS cap instead of
    // ~2 loads/warp in flight.
    float4 rv[8];
    if (live) {
        const float4* r4 = (const float4*)(rep + (size_t)row * DM);
        #pragma unroll
        for (int c = 0; c < 8; c++) rv[c] = r4[c * 32 + lane];
    }

    // cooperative weight load: 2304 float4, 8 per thread (also front-batched)
    {
        const float4* Wm4 = (const float4*)Wm;   // 768 float4
        const float4* Ws4 = (const float4*)Ws;   // 1536 float4
        float4 wv[8];
        #pragma unroll
        for (int c = 0; c < 8; c++) {
            int t2 = c * 288 + tid;
            wv[c] = (t2 < 768) ? Wm4[t2] : Ws4[t2 - 768];
        }
        #pragma unroll
        for (int c = 0; c < 8; c++) sW4[c * 288 + tid] = wv[c];
    }
    __syncthreads();

    if (!live) return;

    float acc[9];
    #pragma unroll
    for (int a = 0; a < 9; a++) acc[a] = 0.0f;

    #pragma unroll
    for (int c = 0; c < 8; c++) {
        int idx = c * 32 + lane;
        float4 r = rv[c];
        #pragma unroll
        for (int a = 0; a < 9; a++) {
            float4 w = sW4[a * 256 + idx];
            acc[a] = fmaf(r.x, w.x, fmaf(r.y, w.y, fmaf(r.z, w.z, fmaf(r.w, w.w, acc[a]))));
        }
    }

    #pragma unroll
    for (int a = 0; a < 9; a++) {
        #pragma unroll
        for (int off = 16; off > 0; off >>= 1)
            acc[a] += __shfl_down_sync(0xffffffffu, acc[a], off);
    }

    if (lane == 0) {
        float mx  = acc[0] + bm[0];
        float my  = acc[1] + bm[1];
        float mz  = acc[2] + bm[2];
        float L00 = softplus_f(acc[3] + bs[0]);
        float L10 = acc[4] + bs[1];
        float L11 = softplus_f(acc[5] + bs[2]);
        float L20 = acc[6] + bs[3];
        float L21 = acc[7] + bs[4];
        float L22 = softplus_f(acc[8] + bs[5]);

        float c = -(logf(L00) + logf(L11) + logf(L22)) - 1.5f * LOG_2PI;

        float4* P = (float4*)(g_params + (size_t)row * 16);
        P[0] = make_float4(mx, my, mz, 1.0f / L00);
        P[1] = make_float4(L10, 1.0f / L11, L20, L21);
        P[2] = make_float4(1.0f / L22, c, 0.0f, 0.0f);

        float* Lout = out + (size_t)NTOT + (size_t)row * 9;
        Lout[0] = L00; Lout[1] = 0.0f; Lout[2] = 0.0f;
        Lout[3] = L10; Lout[4] = L11; Lout[5] = 0.0f;
        Lout[6] = L20; Lout[7] = L21; Lout[8] = L22;
    }
}

// ---------------- kernel 2: profile (PDL secondary) — R8 version ----------------
__device__ __forceinline__ float mvn_eval(float d0, float d1, float d2,
                                          const float4& P0, const float4& P1,
                                          const float4& P2)
{
    float y0 = (d0 - P0.x) * P0.w;
    float y1 = (d1 - P0.y - P1.x * y0) * P1.y;
    float y2 = (d2 - P0.z - P1.z * y0 - P1.w * y1) * P2.x;
    float M  = fmaf(y0, y0, fmaf(y1, y1, y2 * y2));
    return __expf(fmaf(-0.5f, M, P2.y));
}

__device__ __forceinline__ void chunk_eval(unsigned p0, const float* d,
                                           float* __restrict__ out)
{
    unsigned i = p0 / BB;
    unsigned j = p0 - i * BB;
    const float4* P = (const float4*)(g_params + (size_t)i * 16);
    float4 P0 = P[0], P1 = P[1], P2 = P[2];

    float4 res;
    float* rp = &res.x;
    #pragma unroll
    for (int k = 0; k < 4; k++) {
        if (j >= BB) {
            j -= BB;
            P = (const float4*)(g_params + (size_t)(++i) * 16);
            P0 = P[0]; P1 = P[1]; P2 = P[2];
        }
        rp[k] = mvn_eval(d[3*k], d[3*k+1], d[3*k+2], P0, P1, P2);
        j++;
    }
    *(float4*)(out + p0) = res;
}

__device__ __forceinline__ void tail_eval(unsigned pStart,
                                          const float* __restrict__ dxyz,
                                          float* __restrict__ out)
{
    for (unsigned p = pStart; p < NTOT; p++) {
        unsigned i = p / BB;
        const float4* P = (const float4*)(g_params + (size_t)i * 16);
        out[p] = mvn_eval(dxyz[3*p], dxyz[3*p+1], dxyz[3*p+2], P[0], P[1], P[2]);
    }
}

__global__ __launch_bounds__(TPB)
void mvn3d_profile_kernel(const float* __restrict__ dxyz,
                          float* __restrict__ out)
{
    const unsigned t = blockIdx.x * TPB + threadIdx.x;

    const unsigned pA = t * 4;
    const unsigned pB = (t + TTOT) * 4;

    const bool hasB  = (t + TTOT < NCHUNK);
    const bool fullA = (pA + 3 < NTOT);
    const bool fullB = hasB && (pB + 3 < NTOT);

    // front-batch dxyz loads — overlaps with the still-running params kernel
    float4 vA[3], vB[3];
    if (fullA) {
        const float4* dv = (const float4*)(dxyz + (size_t)pA * 3);
        vA[0] = dv[0]; vA[1] = dv[1]; vA[2] = dv[2];
    }
    if (fullB) {
        const float4* dv = (const float4*)(dxyz + (size_t)pB * 3);
        vB[0] = dv[0]; vB[1] = dv[1]; vB[2] = dv[2];
    }

#if __CUDA_ARCH__ >= 900
    cudaGridDependencySynchronize();
#endif

    if (fullA)           chunk_eval(pA, (const float*)vA, out);
    else if (pA < NTOT)  tail_eval(pA, dxyz, out);

    if (fullB)                   chunk_eval(pB, (const float*)vB, out);
    else if (hasB && pB < NTOT)  tail_eval(pB, dxyz, out);
}

extern "C" void kernel_launch(void* const* d_in, const int* in_sizes, int n_in,
                              void* d_out, int out_size) {
    const float* rep  = (const float*)d_in[0];
    const float* dxyz = (const float*)d_in[1];
    const float* Wm   = (const float*)d_in[2];
    const float* bm   = (const float*)d_in[3];
    const float* Ws   = (const float*)d_in[4];
    const float* bs   = (const float*)d_in[5];
    float* out = (float*)d_out;

    mvn3d_params_kernel<<<148, 288>>>(rep, Wm, bm, Ws, bs, out);

    cudaLaunchConfig_t cfg = {};
    cfg.gridDim  = dim3(NBLK);
    cfg.blockDim = dim3(TPB);
    cudaLaunchAttribute attr[1];
    attr[0].id = cudaLaunchAttributeProgrammaticStreamSerialization;
    attr[0].val.programmaticStreamSerializationAllowed = 1;
    cfg.attrs = attr;
    cfg.numAttrs = 1;
    cudaLaunchKernelEx(&cfg, mvn3d_profile_kernel, dxyz, out);
}

// round 14
// speedup vs baseline: 1.0701x; 1.0078x over previous
#include <cuda_runtime.h>
#include <math.h>

#define BB 1323u            // batch == NPTS
#define DM 1024             // DMODEL
#define NTOT (BB * BB)      // 1,750,329 points
#define NCHUNK ((NTOT + 3) / 4)   // 437,583 4-point chunks
#define NBLK 888u                 // 6 CTAs/SM * 148 SMs -> exactly one wave
#define TPB 256u
#define TTOT (NBLK * TPB)         // 227,328 threads
#define LOG_2PI 1.8378770664093453f

__device__ __align__(16) float g_params[BB * 16];

__device__ __forceinline__ float softplus_f(float x) {
    return fmaxf(x, 0.0f) + log1pf(__expf(-fabsf(x)));
}

// ---------------- kernel 1: params. 148 blocks x 9 warps (one block/SM) ----------------
// Publishes the INVERSE Cholesky row form:
//   y0 = a00*d0 + b0 ; y1 = a10*d0 + a11*d1 + b1 ; y2 = a20*d0 + a21*d1 + a22*d2 + b2
// P0 = (a00, a10, a11, a20), P1 = (a21, a22, b0, b1), P2 = (b2, c, -, -)
__global__ __launch_bounds__(288)
void mvn3d_params_kernel(const float* __restrict__ rep,
                         const float* __restrict__ Wm,
                         const float* __restrict__ bm,
                         const float* __restrict__ Ws,
                         const float* __restrict__ bs,
                         float* __restrict__ out)
{
#if __CUDA_ARCH__ >= 900
    cudaTriggerProgrammaticLaunchCompletion();
#endif

    __shared__ __align__(16) float sW[9 * DM];       // 36 KB
    float4* sW4 = (float4*)sW;

    const int tid  = threadIdx.x;
    const int warp = tid >> 5;
    const int lane = tid & 31;

    unsigned row = (unsigned)warp * 148u + blockIdx.x;
    if (warp == 8) row = 1184u + blockIdx.x;
    const bool live = (row < BB);

    // front-batch the full rep row: 8 outstanding LDG.128 per warp
    float4 rv[8];
    if (live) {
        const float4* r4 = (const float4*)(rep + (size_t)row * DM);
        #pragma unroll
        for (int c = 0; c < 8; c++) rv[c] = r4[c * 32 + lane];
    }

    // cooperative weight load: 2304 float4, 8 per thread (front-batched)
    {
        const float4* Wm4 = (const float4*)Wm;   // 768 float4
        const float4* Ws4 = (const float4*)Ws;   // 1536 float4
        float4 wv[8];
        #pragma unroll
        for (int c = 0; c < 8; c++) {
            int t2 = c * 288 + tid;
            wv[c] = (t2 < 768) ? Wm4[t2] : Ws4[t2 - 768];
        }
        #pragma unroll
        for (int c = 0; c < 8; c++) sW4[c * 288 + tid] = wv[c];
    }
    __syncthreads();

    if (!live) return;

    float acc[9];
    #pragma unroll
    for (int a = 0; a < 9; a++) acc[a] = 0.0f;

    #pragma unroll
    for (int c = 0; c < 8; c++) {
        int idx = c * 32 + lane;
        float4 r = rv[c];
        #pragma unroll
        for (int a = 0; a < 9; a++) {
            float4 w = sW4[a * 256 + idx];
            acc[a] = fmaf(r.x, w.x, fmaf(r.y, w.y, fmaf(r.z, w.z, fmaf(r.w, w.w, acc[a]))));
        }
    }

    #pragma unroll
    for (int a = 0; a < 9; a++) {
        #pragma unroll
        for (int off = 16; off > 0; off >>= 1)
            acc[a] += __shfl_down_sync(0xffffffffu, acc[a], off);
    }

    if (lane == 0) {
        float mx  = acc[0] + bm[0];
        float my  = acc[1] + bm[1];
        float mz  = acc[2] + bm[2];
        float L00 = softplus_f(acc[3] + bs[0]);
        float L10 = acc[4] + bs[1];
        float L11 = softplus_f(acc[5] + bs[2]);
        float L20 = acc[6] + bs[3];
        float L21 = acc[7] + bs[4];
        float L22 = softplus_f(acc[8] + bs[5]);

        float c = -(logf(L00) + logf(L11) + logf(L22)) - 1.5f * LOG_2PI;

        // inverse of lower-triangular L
        float a00 = 1.0f / L00;
        float a11 = 1.0f / L11;
        float a22 = 1.0f / L22;
        float a10 = -L10 * a00 * a11;
        float a21 = -L21 * a11 * a22;
        float a20 = (L10 * L21 - L11 * L20) * a00 * a11 * a22;

        // fold means: b = -A * m
        float b0 = -a00 * mx;
        float b1 = -(a10 * mx + a11 * my);
        float b2 = -(a20 * mx + a21 * my + a22 * mz);

        float4* P = (float4*)(g_params + (size_t)row * 16);
        P[0] = make_float4(a00, a10, a11, a20);
        P[1] = make_float4(a21, a22, b0, b1);
        P[2] = make_float4(b2, c, 0.0f, 0.0f);

        float* Lout = out + (size_t)NTOT + (size_t)row * 9;
        Lout[0] = L00; Lout[1] = 0.0f; Lout[2] = 0.0f;
        Lout[3] = L10; Lout[4] = L11; Lout[5] = 0.0f;
        Lout[6] = L20; Lout[7] = L21; Lout[8] = L22;
    }
}

// ---------------- kernel 2: profile (PDL secondary, 6 CTAs/SM single wave) ----------------
__device__ __forceinline__ float mvn_eval(float d0, float d1, float d2,
                                          const float4& P0, const float4& P1,
                                          const float4& P2)
{
    // independent FMA chains (no serial forward substitution)
    float y0 = fmaf(P0.x, d0, P1.z);
    float y1 = fmaf(P0.y, d0, fmaf(P0.z, d1, P1.w));
    float y2 = fmaf(P0.w, d0, fmaf(P1.x, d1, fmaf(P1.y, d2, P2.x)));
    float M  = fmaf(y0, y0, fmaf(y1, y1, y2 * y2));
    return __expf(fmaf(-0.5f, M, P2.y));
}

__device__ __forceinline__ void chunk_eval(unsigned p0, const float* d,
                                           float* __restrict__ out)
{
    unsigned i = p0 / BB;
    unsigned j = p0 - i * BB;
    const float4* P = (const float4*)(g_params + (size_t)i * 16);
    float4 P0 = P[0], P1 = P[1], P2 = P[2];

    float4 res;
    float* rp = &res.x;
    #pragma unroll
    for (int k = 0; k < 4; k++) {
        if (j >= BB) {
            j -= BB;
            P = (const float4*)(g_params + (size_t)(++i) * 16);
            P0 = P[0]; P1 = P[1]; P2 = P[2];
        }
        rp[k] = mvn_eval(d[3*k], d[3*k+1], d[3*k+2], P0, P1, P2);
        j++;
    }
    *(float4*)(out + p0) = res;
}

__device__ __forceinline__ void tail_eval(unsigned pStart,
                                          const float* __restrict__ dxyz,
                                          float* __restrict__ out)
{
    for (unsigned p = pStart; p < NTOT; p++) {
        unsigned i = p / BB;
        const float4* P = (const float4*)(g_params + (size_t)i * 16);
        out[p] = mvn_eval(dxyz[3*p], dxyz[3*p+1], dxyz[3*p+2], P[0], P[1], P[2]);
    }
}

__global__ __launch_bounds__(TPB, 6)
void mvn3d_profile_kernel(const float* __restrict__ dxyz,
                          float* __restrict__ out)
{
    const unsigned t = blockIdx.x * TPB + threadIdx.x;

    const unsigned pA = t * 4;
    const unsigned pB = (t + TTOT) * 4;

    const bool hasB  = (t + TTOT < NCHUNK);
    const bool fullA = (pA + 3 < NTOT);
    const bool fullB = hasB && (pB + 3 < NTOT);

    // front-batch all dxyz loads (up to 6x LDG.128) — overlaps with params kernel
    float4 vA[3], vB[3];
    if (fullA) {
        const float4* dv = (const float4*)(dxyz + (size_t)pA * 3);
        vA[0] = dv[0]; vA[1] = dv[1]; vA[2] = dv[2];
    }
    if (fullB) {
        const float4* dv = (const float4*)(dxyz + (size_t)pB * 3);
        vB[0] = dv[0]; vB[1] = dv[1]; vB[2] = dv[2];
    }

#if __CUDA_ARCH__ >= 900
    cudaGridDependencySynchronize();
#endif

    // store A before computing B to shrink the live register set
    if (fullA)           chunk_eval(pA, (const float*)vA, out);
    else if (pA < NTOT)  tail_eval(pA, dxyz, out);

    if (fullB)                   chunk_eval(pB, (const float*)vB, out);
    else if (hasB && pB < NTOT)  tail_eval(pB, dxyz, out);
}

extern "C" void kernel_launch(void* const* d_in, const int* in_sizes, int n_in,
                              void* d_out, int out_size) {
    const float* rep  = (const float*)d_in[0];
    const float* dxyz = (const float*)d_in[1];
    const float* Wm   = (const float*)d_in[2];
    const float* bm   = (const float*)d_in[3];
    const float* Ws   = (const float*)d_in[4];
    const float* bs   = (const float*)d_in[5];
    float* out = (float*)d_out;

    mvn3d_params_kernel<<<148, 288>>>(rep, Wm, bm, Ws, bs, out);

    cudaLaunchConfig_t cfg = {};
    cfg.gridDim  = dim3(NBLK);
    cfg.blockDim = dim3(TPB);
    cudaLaunchAttribute attr[1];
    attr[0].id = cudaLaunchAttributeProgrammaticStreamSerialization;
    attr[0].val.programmaticStreamSerializationAllowed = 1;
    cfg.attrs = attr;
    cfg.numAttrs = 1;
    cudaLaunchKernelEx(&cfg, mvn3d_profile_kernel, dxyz, out);
}